// round 16
// baseline (speedup 1.0000x reference)
#include <cuda_runtime.h>
#include <cstdint>

// Problem constants
#define NBATCH 64
#define NBINS  256
#define ELEMS_PER_BATCH (256*32*32)          // 262144 floats per batch per tensor
#define F4_PER_BATCH    (ELEMS_PER_BATCH/4)  // 65536 float4
#define CHUNKS 8                             // blocks per (batch, tensor)
#define F4_PER_CHUNK (F4_PER_BATCH/CHUNKS)   // 8192 float4 per block
#define HIST_THREADS 512
#define BLOCKS_PER_BATCH (2*CHUNKS)          // 16 (both tensors)
#define BF4 4                                // float4 per pipeline stage
#define STEP (BF4*HIST_THREADS)              // f4 consumed per stage (2048)
#define NSTEPS (F4_PER_CHUNK/STEP)           // 4 stages per block

// Scratch (no device allocation allowed).
__device__ unsigned int g_part[2][NBATCH][CHUNKS][NBINS];
__device__ float        g_kl[NBATCH];
__device__ unsigned int g_bctr[NBATCH];      // per-batch tickets (reset by winner)
__device__ unsigned int g_ctr;               // global ticket (reset by final block)

// Exact float->small-int for integer-valued f in [0,255]: low byte of
// bits(f + 2^23). FADD+LOP instead of the F2I conversion pipe.
__device__ __forceinline__ unsigned int bin_of(float f) {
    return __float_as_uint(f + 8388608.0f) & 0xFFu;
}

// ---------------------------------------------------------------------------
// Single fused kernel. grid = (CHUNKS, NBATCH, 2) = 1024 blocks, block = 512.
// 2 blocks/SM resident, ~3.5 waves: fine-grained blocks let the scheduler
// balance atomic-lane work across SMs (the 256-block version wave-quantizes
// at +15.6% over the ideal ATOMS floor — 108 SMs get 2 blocks, 40 get 1).
// Inner loop: software-pipelined register double buffer (4 float4/stage) so
// the ATOMS unit (measured wall ~4.2 lane-ops/cyc/SM) never drains.
// Hist layout sh[bin][lane]: bank-exclusive, conflict-free by construction.
// ---------------------------------------------------------------------------
__global__ void __launch_bounds__(HIST_THREADS, 2) fused_kernel(
    const float4* __restrict__ feat_s, const float4* __restrict__ feat_t,
    float* __restrict__ out) {

    __shared__ unsigned int sh[NBINS][32];   // 32 KB: [bin][lane-column]

    #pragma unroll
    for (int i = threadIdx.x; i < NBINS * 32; i += HIST_THREADS)
        (&sh[0][0])[i] = 0u;
    __syncthreads();

    const float4* __restrict__ src = (blockIdx.z == 0) ? feat_s : feat_t;
    const int batch = blockIdx.y;
    const size_t base = (size_t)batch * F4_PER_BATCH
                      + (size_t)blockIdx.x * F4_PER_CHUNK;
    const int lane = threadIdx.x & 31;
    const float4* g = src + base + threadIdx.x;

    float4 a[BF4], b[BF4];

    // prologue: stage 0 into 'a'
    #pragma unroll
    for (int k = 0; k < BF4; k++)
        a[k] = __ldcs(&g[k * HIST_THREADS]);

    // main: unrolled x2, alternating buffers; loads for stage s+1 issued
    // before the atomics of stage s.
    #pragma unroll 1
    for (int s = 0; s < NSTEPS - 2; s += 2) {
        const float4* gn1 = g + (size_t)(s + 1) * STEP;
        #pragma unroll
        for (int k = 0; k < BF4; k++) b[k] = __ldcs(&gn1[k * HIST_THREADS]);
        #pragma unroll
        for (int k = 0; k < BF4; k++) {
            atomicAdd(&sh[bin_of(a[k].x)][lane], 1u);
            atomicAdd(&sh[bin_of(a[k].y)][lane], 1u);
            atomicAdd(&sh[bin_of(a[k].z)][lane], 1u);
            atomicAdd(&sh[bin_of(a[k].w)][lane], 1u);
        }
        const float4* gn2 = g + (size_t)(s + 2) * STEP;
        #pragma unroll
        for (int k = 0; k < BF4; k++) a[k] = __ldcs(&gn2[k * HIST_THREADS]);
        #pragma unroll
        for (int k = 0; k < BF4; k++) {
            atomicAdd(&sh[bin_of(b[k].x)][lane], 1u);
            atomicAdd(&sh[bin_of(b[k].y)][lane], 1u);
            atomicAdd(&sh[bin_of(b[k].z)][lane], 1u);
            atomicAdd(&sh[bin_of(b[k].w)][lane], 1u);
        }
    }
    // epilogue: stages NSTEPS-2 (in 'a') and NSTEPS-1
    {
        const float4* gn = g + (size_t)(NSTEPS - 1) * STEP;
        #pragma unroll
        for (int k = 0; k < BF4; k++) b[k] = __ldcs(&gn[k * HIST_THREADS]);
        #pragma unroll
        for (int k = 0; k < BF4; k++) {
            atomicAdd(&sh[bin_of(a[k].x)][lane], 1u);
            atomicAdd(&sh[bin_of(a[k].y)][lane], 1u);
            atomicAdd(&sh[bin_of(a[k].z)][lane], 1u);
            atomicAdd(&sh[bin_of(a[k].w)][lane], 1u);
        }
        #pragma unroll
        for (int k = 0; k < BF4; k++) {
            atomicAdd(&sh[bin_of(b[k].x)][lane], 1u);
            atomicAdd(&sh[bin_of(b[k].y)][lane], 1u);
            atomicAdd(&sh[bin_of(b[k].z)][lane], 1u);
            atomicAdd(&sh[bin_of(b[k].w)][lane], 1u);
        }
    }
    __syncthreads();

    // reduce 32 lane-columns per bin; rotated reads keep banks conflict-free
    if (threadIdx.x < NBINS) {
        const int bb = threadIdx.x;
        unsigned int sum = 0;
        #pragma unroll
        for (int i = 0; i < 32; i++) sum += sh[bb][(i + bb) & 31];
        g_part[blockIdx.z][batch][blockIdx.x][bb] = sum;
    }
    __syncthreads();

    // ---- per-batch ticket ----
    __shared__ unsigned int s_bticket;
    if (threadIdx.x == 0) {
        __threadfence();
        s_bticket = atomicAdd(&g_bctr[batch], 1u);
    }
    __syncthreads();
    if (s_bticket != BLOCKS_PER_BATCH - 1) return;

    // ======== this block is last for its batch: compute KL(batch) ========
    __threadfence();  // acquire: make all partials of this batch visible

    const int bn = threadIdx.x;           // bin id for threads < NBINS
    __shared__ float rs[NBINS];
    __shared__ float rt[NBINS];

    float es = 0.f, et = 0.f, as_ = 0.f, at_ = 0.f;
    if (bn < NBINS) {
        unsigned int cs = 0, ct = 0;
        #pragma unroll
        for (int c = 0; c < CHUNKS; c++) {
            cs += *((volatile unsigned int*)&g_part[0][batch][c][bn]);
            ct += *((volatile unsigned int*)&g_part[1][batch][c][bn]);
        }
        as_ = (float)cs + 1e-8f;
        at_ = (float)ct + 1e-8f;
        es = sqrtf(sqrtf(as_));           // (a)^(1/T), T = 4
        et = sqrtf(sqrtf(at_));
        rs[bn] = es; rt[bn] = et;
    }
    __syncthreads();
    #pragma unroll
    for (int s = NBINS / 2; s > 0; s >>= 1) {
        if (bn < s) { rs[bn] += rs[bn + s]; rt[bn] += rt[bn + s]; }
        __syncthreads();
    }
    float Ss = rs[0];
    float St = rt[0];
    __syncthreads();

    if (bn < NBINS) {
        float pt = et / St;                                   // softmax target
        float diff = 0.25f * logf(at_ / as_) - logf(St / Ss); // log p_t - log p_s
        rs[bn] = pt * diff;
    }
    __syncthreads();
    #pragma unroll
    for (int s = NBINS / 2; s > 0; s >>= 1) {
        if (bn < s) rs[bn] += rs[bn + s];
        __syncthreads();
    }

    // publish per-batch KL, reset batch ticket, take global ticket
    __shared__ unsigned int s_ticket;
    if (threadIdx.x == 0) {
        g_kl[batch] = rs[0];
        g_bctr[batch] = 0;                 // ready for next graph replay
        __threadfence();
        s_ticket = atomicAdd(&g_ctr, 1u);
    }
    __syncthreads();
    if (s_ticket != NBATCH - 1) return;

    // ======== very last batch-winner: deterministic final sum ========
    __threadfence();
    __shared__ float red[NBATCH];
    if (threadIdx.x < NBATCH) red[threadIdx.x] = *((volatile float*)&g_kl[threadIdx.x]);
    __syncthreads();
    #pragma unroll
    for (int s = NBATCH / 2; s > 0; s >>= 1) {
        if (threadIdx.x < s) red[threadIdx.x] += red[threadIdx.x + s];
        __syncthreads();
    }
    if (threadIdx.x == 0) {
        out[0] = red[0] * (16.0f / (float)NBATCH);  // * T^2 / N
        g_ctr = 0;                                  // ready for next replay
    }
}

// ---------------------------------------------------------------------------
extern "C" void kernel_launch(void* const* d_in, const int* in_sizes, int n_in,
                              void* d_out, int out_size) {
    const float4* feat_s = (const float4*)d_in[0];
    const float4* feat_t = (const float4*)d_in[1];
    float* out = (float*)d_out;

    (void)in_sizes; (void)n_in; (void)out_size;

    dim3 grid(CHUNKS, NBATCH, 2);
    fused_kernel<<<grid, HIST_THREADS>>>(feat_s, feat_t, out);
}